// round 2
// baseline (speedup 1.0000x reference)
#include <cuda_runtime.h>
#include <cstddef>

#define NUSER 100000
#define NITEM 100000
#define NEDGE 600000
#define HDIM  128
#define LN_EPS 1e-5f

// ---------------- scratch (device globals; no allocation allowed) ----------------
__device__ __align__(128) float g_hu   [(size_t)NUSER * HDIM];
__device__ __align__(128) float g_hi   [(size_t)NITEM * HDIM];
__device__ __align__(128) float g_hu1  [(size_t)NUSER * HDIM];
__device__ __align__(128) float g_hi1  [(size_t)NITEM * HDIM];
__device__ __align__(128) float g_agg_u[(size_t)NUSER * HDIM];
__device__ __align__(128) float g_agg_i[(size_t)NITEM * HDIM];
__device__ __align__(128) float g_cnt_u[NUSER];
__device__ __align__(128) float g_cnt_i[NITEM];

// ---------------- helpers ----------------
__global__ void zero_kernel(float* __restrict__ agg, float* __restrict__ cnt, int n) {
    int i = blockIdx.x * blockDim.x + threadIdx.x;
    int nagg = n * HDIM;
    if (i < nagg) agg[i] = 0.f;
    int j = i - nagg;
    if (j >= 0 && j < n) cnt[j] = 0.f;
}

// one warp per edge; each lane handles 4 contiguous features (float4 gather, 4 atomics)
__global__ void scatter_kernel(const float* __restrict__ src_feat, const int* __restrict__ edge,
                               float* __restrict__ agg, float* __restrict__ cnt) {
    int gid = blockIdx.x * blockDim.x + threadIdx.x;
    int e = gid >> 5;
    if (e >= NEDGE) return;
    int lane = gid & 31;
    int s = __ldg(edge + e);          // row 0: src index
    int d = __ldg(edge + NEDGE + e);  // row 1: dst index
    float4 v = *reinterpret_cast<const float4*>(src_feat + (size_t)s * HDIM + lane * 4);
    float* dp = agg + (size_t)d * HDIM + lane * 4;
    atomicAdd(dp + 0, v.x);
    atomicAdd(dp + 1, v.y);
    atomicAdd(dp + 2, v.z);
    atomicAdd(dp + 3, v.w);
    if (lane == 0) atomicAdd(cnt + d, 1.0f);
}

__global__ void div_kernel(float* __restrict__ agg, const float* __restrict__ cnt, int n) {
    int i = blockIdx.x * blockDim.x + threadIdx.x;
    if (i < n * HDIM) {
        float c = cnt[i >> 7];  // HDIM == 128
        agg[i] = agg[i] / fmaxf(c, 1.0f);
    }
}

// ---------------- fused GEMM + epilogue ----------------
// C[M,N] = epi( A1[M,K1] @ W1[K1,N] + A2[M,KTOT-K1] @ W2[KTOT-K1,N] + bias )
// EPI: 0 = bias + ReLU, 1 = bias + LayerNorm + ReLU, 2 = bias + LayerNorm
// Tile: 128 rows x N cols per CTA, 256 threads (16x16), per-thread 8 x (N/16).
// Requires K1 % 32 == 0 and KTOT % 32 == 0 (true: 96,160,128,256).
template<int N, int EPI>
__launch_bounds__(256, 2)
__global__ void gemm_epi_kernel(
    const float* __restrict__ A1, const float* __restrict__ A2,
    const float* __restrict__ W1, const float* __restrict__ W2,
    int K1, int KTOT,
    const float* __restrict__ bias,
    const float* __restrict__ gamma, const float* __restrict__ beta,
    float* __restrict__ C, int M)
{
    constexpr int TN = N / 16;
    __shared__ float As[32][132];   // [k][row], padded
    __shared__ float Ws[32][N];     // [k][n]

    const int t  = threadIdx.x;
    const int tx = t & 15;
    const int ty = t >> 4;
    const int m0 = blockIdx.x * 128;

    float acc[8][TN];
    #pragma unroll
    for (int i = 0; i < 8; i++)
        #pragma unroll
        for (int j = 0; j < TN; j++) acc[i][j] = 0.f;

    for (int kc = 0; kc < KTOT; kc += 32) {
        const bool first = (kc < K1);
        const float* Ap = first ? A1 : A2;
        const float* Wp = first ? W1 : W2;
        const int kb = first ? kc : (kc - K1);
        const int Ka = first ? K1 : (KTOT - K1);

        // load A chunk (128 rows x 32 k), transposed into As[k][row]
        #pragma unroll
        for (int q = 0; q < 4; q++) {
            int idx = t * 4 + q;         // 0..1023 float4s
            int row = idx >> 3;          // 0..127
            int kq  = (idx & 7) * 4;     // 0..28
            float4 v = make_float4(0.f, 0.f, 0.f, 0.f);
            if (m0 + row < M)
                v = *reinterpret_cast<const float4*>(Ap + (size_t)(m0 + row) * Ka + kb + kq);
            As[kq + 0][row] = v.x;
            As[kq + 1][row] = v.y;
            As[kq + 2][row] = v.z;
            As[kq + 3][row] = v.w;
        }
        // load W chunk (32 x N), contiguous copy
        {
            constexpr int WF4 = 32 * N / 4;
            const float4* wsrc = reinterpret_cast<const float4*>(Wp + (size_t)kb * N);
            float4* wdst = reinterpret_cast<float4*>(&Ws[0][0]);
            #pragma unroll
            for (int i = t; i < WF4; i += 256) wdst[i] = wsrc[i];
        }
        __syncthreads();

        #pragma unroll
        for (int k = 0; k < 32; k++) {
            float a[8], w[TN];
            #pragma unroll
            for (int i = 0; i < 8; i++) a[i] = As[k][ty + 16 * i];
            #pragma unroll
            for (int j = 0; j < TN; j++) w[j] = Ws[k][tx * TN + j];
            #pragma unroll
            for (int i = 0; i < 8; i++)
                #pragma unroll
                for (int j = 0; j < TN; j++)
                    acc[i][j] = fmaf(a[i], w[j], acc[i][j]);
        }
        __syncthreads();
    }

    // ---- epilogue ----
    float bv[TN], gv[TN], btv[TN];
    #pragma unroll
    for (int j = 0; j < TN; j++) bv[j] = __ldg(bias + tx * TN + j);
    if (EPI >= 1) {
        #pragma unroll
        for (int j = 0; j < TN; j++) {
            gv[j]  = __ldg(gamma + tx * TN + j);
            btv[j] = __ldg(beta  + tx * TN + j);
        }
    }

    #pragma unroll
    for (int i = 0; i < 8; i++) {
        int row = m0 + ty + 16 * i;
        float v[TN];
        #pragma unroll
        for (int j = 0; j < TN; j++) v[j] = acc[i][j] + bv[j];

        if (EPI >= 1) {
            // LayerNorm over N cols owned by the 16 threads sharing this row
            float s = 0.f;
            #pragma unroll
            for (int j = 0; j < TN; j++) s += v[j];
            #pragma unroll
            for (int o = 8; o > 0; o >>= 1) s += __shfl_xor_sync(0xffffffffu, s, o, 16);
            float mean = s * (1.0f / N);
            float q = 0.f;
            #pragma unroll
            for (int j = 0; j < TN; j++) { float d = v[j] - mean; q += d * d; }
            #pragma unroll
            for (int o = 8; o > 0; o >>= 1) q += __shfl_xor_sync(0xffffffffu, q, o, 16);
            float rstd = rsqrtf(q * (1.0f / N) + LN_EPS);
            #pragma unroll
            for (int j = 0; j < TN; j++) {
                v[j] = (v[j] - mean) * rstd * gv[j] + btv[j];
                if (EPI == 1) v[j] = fmaxf(v[j], 0.f);
            }
        } else {
            #pragma unroll
            for (int j = 0; j < TN; j++) v[j] = fmaxf(v[j], 0.f);
        }

        if (row < M) {
            float* cp = C + (size_t)row * N + tx * TN;
            #pragma unroll
            for (int j = 0; j < TN; j += 4)
                *reinterpret_cast<float4*>(cp + j) =
                    make_float4(v[j], v[j + 1], v[j + 2], v[j + 3]);
        }
    }
}

// ---------------- host ----------------
extern "C" void kernel_launch(void* const* d_in, const int* in_sizes, int n_in,
                              void* d_out, int out_size) {
    (void)in_sizes; (void)n_in; (void)out_size;

    const float* x_user  = (const float*)d_in[0];
    const float* x_item  = (const float*)d_in[1];
    const int*   edge_ui = (const int*)d_in[2];
    const int*   edge_iu = (const int*)d_in[3];
    const float* Wp_u   = (const float*)d_in[4];
    const float* bp_u   = (const float*)d_in[5];
    const float* Wp_i   = (const float*)d_in[6];
    const float* bp_i   = (const float*)d_in[7];
    const float* Wl0_ui = (const float*)d_in[8];
    const float* bl0_ui = (const float*)d_in[9];
    const float* Wr0_ui = (const float*)d_in[10];
    const float* Wl0_iu = (const float*)d_in[11];
    const float* bl0_iu = (const float*)d_in[12];
    const float* Wr0_iu = (const float*)d_in[13];
    const float* g0_u   = (const float*)d_in[14];
    const float* b0_u   = (const float*)d_in[15];
    const float* g0_i   = (const float*)d_in[16];
    const float* b0_i   = (const float*)d_in[17];
    const float* Wl1_ui = (const float*)d_in[18];
    const float* bl1_ui = (const float*)d_in[19];
    const float* Wr1_ui = (const float*)d_in[20];
    const float* Wl1_iu = (const float*)d_in[21];
    const float* bl1_iu = (const float*)d_in[22];
    const float* Wr1_iu = (const float*)d_in[23];
    const float* g1_u   = (const float*)d_in[24];
    const float* b1_u   = (const float*)d_in[25];
    const float* g1_i   = (const float*)d_in[26];
    const float* b1_i   = (const float*)d_in[27];

    float* out = (float*)d_out;
    float* out_u = out;                            // h_u2: [NUSER, 64]
    float* out_i = out + (size_t)NUSER * 64;       // h_i2: [NITEM, 64]

    float *hu, *hi, *hu1, *hi1, *aggu, *aggi, *cntu, *cnti;
    cudaGetSymbolAddress((void**)&hu,   g_hu);
    cudaGetSymbolAddress((void**)&hi,   g_hi);
    cudaGetSymbolAddress((void**)&hu1,  g_hu1);
    cudaGetSymbolAddress((void**)&hi1,  g_hi1);
    cudaGetSymbolAddress((void**)&aggu, g_agg_u);
    cudaGetSymbolAddress((void**)&aggi, g_agg_i);
    cudaGetSymbolAddress((void**)&cntu, g_cnt_u);
    cudaGetSymbolAddress((void**)&cnti, g_cnt_i);

    const int gmU = (NUSER + 127) / 128;
    const int gmI = (NITEM + 127) / 128;
    const int zgU = (NUSER * (HDIM + 1) + 255) / 256;
    const int zgI = (NITEM * (HDIM + 1) + 255) / 256;
    const int dgU = (NUSER * HDIM + 255) / 256;
    const int dgI = (NITEM * HDIM + 255) / 256;
    const int sg  = (NEDGE * 32 + 255) / 256;

    // input projections + ReLU
    gemm_epi_kernel<128, 0><<<gmU, 256>>>(x_user, x_user, Wp_u, Wp_u, 96, 96,
                                          bp_u, nullptr, nullptr, hu, NUSER);
    gemm_epi_kernel<128, 0><<<gmI, 256>>>(x_item, x_item, Wp_i, Wp_i, 160, 160,
                                          bp_i, nullptr, nullptr, hi, NITEM);

    // layer 0 aggregations (seg-mean)
    zero_kernel<<<zgI, 256>>>(aggi, cnti, NITEM);
    scatter_kernel<<<sg, 256>>>(hu, edge_ui, aggi, cnti);
    div_kernel<<<dgI, 256>>>(aggi, cnti, NITEM);

    zero_kernel<<<zgU, 256>>>(aggu, cntu, NUSER);
    scatter_kernel<<<sg, 256>>>(hi, edge_iu, aggu, cntu);
    div_kernel<<<dgU, 256>>>(aggu, cntu, NUSER);

    // layer 0 combine: agg@Wl + h@Wr + bl -> LN -> ReLU
    gemm_epi_kernel<128, 1><<<gmI, 256>>>(aggi, hi, Wl0_ui, Wr0_ui, 128, 256,
                                          bl0_ui, g0_i, b0_i, hi1, NITEM);
    gemm_epi_kernel<128, 1><<<gmU, 256>>>(aggu, hu, Wl0_iu, Wr0_iu, 128, 256,
                                          bl0_iu, g0_u, b0_u, hu1, NUSER);

    // layer 1 aggregations
    zero_kernel<<<zgI, 256>>>(aggi, cnti, NITEM);
    scatter_kernel<<<sg, 256>>>(hu1, edge_ui, aggi, cnti);
    div_kernel<<<dgI, 256>>>(aggi, cnti, NITEM);

    zero_kernel<<<zgU, 256>>>(aggu, cntu, NUSER);
    scatter_kernel<<<sg, 256>>>(hi1, edge_iu, aggu, cntu);
    div_kernel<<<dgU, 256>>>(aggu, cntu, NUSER);

    // layer 1 combine: agg@Wl + h@Wr + bl -> LN (no ReLU), write straight to d_out
    gemm_epi_kernel<64, 2><<<gmI, 256>>>(aggi, hi1, Wl1_ui, Wr1_ui, 128, 256,
                                         bl1_ui, g1_i, b1_i, out_i, NITEM);
    gemm_epi_kernel<64, 2><<<gmU, 256>>>(aggu, hu1, Wl1_iu, Wr1_iu, 128, 256,
                                         bl1_iu, g1_u, b1_u, out_u, NUSER);
}

// round 3
// speedup vs baseline: 2.2892x; 2.2892x over previous
#include <cuda_runtime.h>
#include <cstddef>

#define NUSER 100000
#define NITEM 100000
#define NEDGE 600000
#define HDIM  128
#define LN_EPS 1e-5f

// ---------------- scratch (device globals; no allocation allowed) ----------------
__device__ __align__(128) float g_hu [(size_t)NUSER * HDIM];   // h_u, then h_u1
__device__ __align__(128) float g_hi [(size_t)NITEM * HDIM];   // h_i, then h_i1
__device__ __align__(128) float g_Mu [(size_t)NUSER * HDIM];   // h_u@Wl0_ui   / P_u (64)
__device__ __align__(128) float g_Qu [(size_t)NUSER * HDIM];   // h_u@Wr0_iu   / R_u (64)
__device__ __align__(128) float g_Mi [(size_t)NITEM * HDIM];   // h_i@Wl0_iu   / P_i (64)
__device__ __align__(128) float g_Qi [(size_t)NITEM * HDIM];   // h_i@Wr0_ui   / R_i (64)

__device__ int g_deg_u[NUSER], g_deg_i[NITEM];
__device__ int g_cur_u[NUSER], g_cur_i[NITEM];
__device__ int g_ptr_u[NUSER + 1], g_ptr_i[NITEM + 1];
__device__ int g_col_u[NEDGE], g_col_i[NEDGE];

// ---------------- small helpers ----------------
__device__ __forceinline__ unsigned f2tf(float x) {
    unsigned r;
    asm("cvt.rna.tf32.f32 %0, %1;" : "=r"(r) : "f"(x));
    return r;
}

__device__ __forceinline__ void mma8(float* c, const unsigned* a, const unsigned* b) {
    asm volatile(
        "mma.sync.aligned.m16n8k8.row.col.f32.tf32.tf32.f32 "
        "{%0,%1,%2,%3}, {%4,%5,%6,%7}, {%8,%9}, {%0,%1,%2,%3};"
        : "+f"(c[0]), "+f"(c[1]), "+f"(c[2]), "+f"(c[3])
        : "r"(a[0]), "r"(a[1]), "r"(a[2]), "r"(a[3]), "r"(b[0]), "r"(b[1]));
}

// ---------------- CSR build ----------------
__global__ void zero4_kernel(int* a, int* b, int* c, int* d, int n) {
    int i = blockIdx.x * blockDim.x + threadIdx.x;
    if (i < n) { a[i] = 0; b[i] = 0; c[i] = 0; d[i] = 0; }
}

__global__ void hist_kernel(const int* __restrict__ edge, int* __restrict__ deg) {
    int e = blockIdx.x * blockDim.x + threadIdx.x;
    if (e < NEDGE) atomicAdd(&deg[__ldg(edge + NEDGE + e)], 1);
}

// single block, 1024 threads: exclusive scan of deg[0..n) into ptr[0..n]
__global__ void scan_kernel(const int* __restrict__ deg, int* __restrict__ ptr, int n) {
    __shared__ int s[1024];
    int t = threadIdx.x;
    int CH = (n + 1023) >> 10;
    int lo = t * CH, hi = min(lo + CH, n);
    int sum = 0;
    for (int i = lo; i < hi; i++) sum += deg[i];
    s[t] = sum;
    __syncthreads();
    for (int off = 1; off < 1024; off <<= 1) {
        int v = (t >= off) ? s[t - off] : 0;
        __syncthreads();
        s[t] += v;
        __syncthreads();
    }
    int base = s[t] - sum;
    for (int i = lo; i < hi; i++) { ptr[i] = base; base += deg[i]; }
    if (t == 1023) ptr[n] = s[1023];
}

__global__ void fill_kernel(const int* __restrict__ edge, const int* __restrict__ ptr,
                            int* __restrict__ cur, int* __restrict__ col) {
    int e = blockIdx.x * blockDim.x + threadIdx.x;
    if (e >= NEDGE) return;
    int d = __ldg(edge + NEDGE + e);
    int p = atomicAdd(&cur[d], 1);
    col[__ldg(ptr + d) + p] = __ldg(edge + e);
}

// ---------------- TF32 tensor-core GEMM: C[M,BN] = A[M,K] @ W[K,BN] (+bias,ReLU) ----------------
// BM=128, BK=32, 256 threads. BN=128: warps 2x4 (64x32 each). BN=64: warps 4x2 (32x32).
template<int BN, bool BIASRELU>
__launch_bounds__(256, 2)
__global__ void gemm_tf32_kernel(const float* __restrict__ A, const float* __restrict__ W,
                                 const float* __restrict__ bias, float* __restrict__ C,
                                 int M, int K)
{
    constexpr int WM = (BN == 128) ? 64 : 32;
    constexpr int WARPS_N = BN / 32;
    constexpr int MT = WM / 16;
    constexpr int NT = 4;

    __shared__ unsigned As[128][36];     // [m][k], pad 4
    __shared__ unsigned Bs[32][BN + 8];  // [k][n], pad 8

    const int t = threadIdx.x;
    const int w = t >> 5, lane = t & 31;
    const int g = lane >> 2, tg = lane & 3;
    const int wm = w / WARPS_N, wn = w % WARPS_N;
    const int m0 = blockIdx.x * 128;

    float acc[MT][NT][4];
    #pragma unroll
    for (int mt = 0; mt < MT; mt++)
        #pragma unroll
        for (int nt = 0; nt < NT; nt++)
            #pragma unroll
            for (int j = 0; j < 4; j++) acc[mt][nt][j] = 0.f;

    for (int kc = 0; kc < K; kc += 32) {
        // A tile: 128 rows x 32 k, converted to tf32
        #pragma unroll
        for (int q = 0; q < 4; q++) {
            int idx = t * 4 + q;
            int row = idx >> 3;
            int kq = (idx & 7) * 4;
            float4 v = make_float4(0.f, 0.f, 0.f, 0.f);
            if (m0 + row < M)
                v = *reinterpret_cast<const float4*>(A + (size_t)(m0 + row) * K + kc + kq);
            As[row][kq + 0] = f2tf(v.x);
            As[row][kq + 1] = f2tf(v.y);
            As[row][kq + 2] = f2tf(v.z);
            As[row][kq + 3] = f2tf(v.w);
        }
        // W tile: 32 x BN
        constexpr int WF4 = 32 * BN / 4;
        #pragma unroll
        for (int i = t; i < WF4; i += 256) {
            int k = i / (BN / 4);
            int n4 = (i % (BN / 4)) * 4;
            float4 v = *reinterpret_cast<const float4*>(W + (size_t)(kc + k) * BN + n4);
            Bs[k][n4 + 0] = f2tf(v.x);
            Bs[k][n4 + 1] = f2tf(v.y);
            Bs[k][n4 + 2] = f2tf(v.z);
            Bs[k][n4 + 3] = f2tf(v.w);
        }
        __syncthreads();

        #pragma unroll
        for (int kk = 0; kk < 32; kk += 8) {
            unsigned a[MT][4], b[NT][2];
            #pragma unroll
            for (int mt = 0; mt < MT; mt++) {
                int r = wm * WM + mt * 16 + g;
                a[mt][0] = As[r][kk + tg];
                a[mt][1] = As[r + 8][kk + tg];
                a[mt][2] = As[r][kk + tg + 4];
                a[mt][3] = As[r + 8][kk + tg + 4];
            }
            #pragma unroll
            for (int nt = 0; nt < NT; nt++) {
                int c = wn * 32 + nt * 8 + g;
                b[nt][0] = Bs[kk + tg][c];
                b[nt][1] = Bs[kk + tg + 4][c];
            }
            #pragma unroll
            for (int mt = 0; mt < MT; mt++)
                #pragma unroll
                for (int nt = 0; nt < NT; nt++)
                    mma8(acc[mt][nt], a[mt], b[nt]);
        }
        __syncthreads();
    }

    // epilogue: direct float2 stores from fragments
    #pragma unroll
    for (int mt = 0; mt < MT; mt++) {
        int r0 = m0 + wm * WM + mt * 16 + g;
        #pragma unroll
        for (int nt = 0; nt < NT; nt++) {
            int c = wn * 32 + nt * 8 + 2 * tg;
            float x0 = acc[mt][nt][0], x1 = acc[mt][nt][1];
            float x2 = acc[mt][nt][2], x3 = acc[mt][nt][3];
            if (BIASRELU) {
                float b0 = __ldg(bias + c), b1 = __ldg(bias + c + 1);
                x0 = fmaxf(x0 + b0, 0.f); x1 = fmaxf(x1 + b1, 0.f);
                x2 = fmaxf(x2 + b0, 0.f); x3 = fmaxf(x3 + b1, 0.f);
            }
            if (r0 < M)
                *reinterpret_cast<float2*>(C + (size_t)r0 * BN + c) = make_float2(x0, x1);
            if (r0 + 8 < M)
                *reinterpret_cast<float2*>(C + (size_t)(r0 + 8) * BN + c) = make_float2(x2, x3);
        }
    }
}

// ---------------- fused CSR gather-mean + self + bias + LN (+ReLU) ----------------
// one warp per destination node; VPL floats per lane (C = 32*VPL)
template<int VPL, bool RELU>
__global__ void aggfin_kernel(const float* __restrict__ msg, const float* __restrict__ self,
                              const int* __restrict__ ptr, const int* __restrict__ col,
                              const float* __restrict__ bias,
                              const float* __restrict__ gamma, const float* __restrict__ beta,
                              float* __restrict__ out, int n)
{
    constexpr int C = 32 * VPL;
    int gw = (blockIdx.x * blockDim.x + threadIdx.x) >> 5;
    if (gw >= n) return;
    int lane = threadIdx.x & 31;

    int p0 = __ldg(ptr + gw), p1 = __ldg(ptr + gw + 1);
    float v[VPL];
    #pragma unroll
    for (int j = 0; j < VPL; j++) v[j] = 0.f;

    for (int e = p0; e < p1; e++) {
        int s = __ldg(col + e);
        const float* mp = msg + (size_t)s * C + lane * VPL;
        if (VPL == 4) {
            float4 t4 = *reinterpret_cast<const float4*>(mp);
            v[0] += t4.x; v[1] += t4.y; v[2 % VPL] += t4.z; v[3 % VPL] += t4.w;
        } else {
            float2 t2 = *reinterpret_cast<const float2*>(mp);
            v[0] += t2.x; v[1 % VPL] += t2.y;
        }
    }
    float inv = 1.f / fmaxf((float)(p1 - p0), 1.f);

    const float* sp = self + (size_t)gw * C + lane * VPL;
    if (VPL == 4) {
        float4 s4 = *reinterpret_cast<const float4*>(sp);
        v[0] = v[0] * inv + s4.x; v[1] = v[1] * inv + s4.y;
        v[2 % VPL] = v[2 % VPL] * inv + s4.z; v[3 % VPL] = v[3 % VPL] * inv + s4.w;
    } else {
        float2 s2 = *reinterpret_cast<const float2*>(sp);
        v[0] = v[0] * inv + s2.x; v[1 % VPL] = v[1 % VPL] * inv + s2.y;
    }
    #pragma unroll
    for (int j = 0; j < VPL; j++) v[j] += __ldg(bias + lane * VPL + j);

    // LayerNorm across the warp (row fully within warp)
    float s = 0.f;
    #pragma unroll
    for (int j = 0; j < VPL; j++) s += v[j];
    #pragma unroll
    for (int o = 16; o > 0; o >>= 1) s += __shfl_xor_sync(0xffffffffu, s, o);
    float mean = s * (1.f / C);
    float q = 0.f;
    #pragma unroll
    for (int j = 0; j < VPL; j++) { float d = v[j] - mean; q += d * d; }
    #pragma unroll
    for (int o = 16; o > 0; o >>= 1) q += __shfl_xor_sync(0xffffffffu, q, o);
    float rstd = rsqrtf(q * (1.f / C) + LN_EPS);

    float* op = out + (size_t)gw * C + lane * VPL;
    float ov[VPL];
    #pragma unroll
    for (int j = 0; j < VPL; j++) {
        float x = (v[j] - mean) * rstd * __ldg(gamma + lane * VPL + j) + __ldg(beta + lane * VPL + j);
        ov[j] = RELU ? fmaxf(x, 0.f) : x;
    }
    if (VPL == 4)
        *reinterpret_cast<float4*>(op) = make_float4(ov[0], ov[1], ov[2 % VPL], ov[3 % VPL]);
    else
        *reinterpret_cast<float2*>(op) = make_float2(ov[0], ov[1 % VPL]);
}

// ---------------- host ----------------
extern "C" void kernel_launch(void* const* d_in, const int* in_sizes, int n_in,
                              void* d_out, int out_size) {
    (void)in_sizes; (void)n_in; (void)out_size;

    const float* x_user  = (const float*)d_in[0];
    const float* x_item  = (const float*)d_in[1];
    const int*   edge_ui = (const int*)d_in[2];
    const int*   edge_iu = (const int*)d_in[3];
    const float* Wp_u   = (const float*)d_in[4];
    const float* bp_u   = (const float*)d_in[5];
    const float* Wp_i   = (const float*)d_in[6];
    const float* bp_i   = (const float*)d_in[7];
    const float* Wl0_ui = (const float*)d_in[8];
    const float* bl0_ui = (const float*)d_in[9];
    const float* Wr0_ui = (const float*)d_in[10];
    const float* Wl0_iu = (const float*)d_in[11];
    const float* bl0_iu = (const float*)d_in[12];
    const float* Wr0_iu = (const float*)d_in[13];
    const float* g0_u   = (const float*)d_in[14];
    const float* b0_u   = (const float*)d_in[15];
    const float* g0_i   = (const float*)d_in[16];
    const float* b0_i   = (const float*)d_in[17];
    const float* Wl1_ui = (const float*)d_in[18];
    const float* bl1_ui = (const float*)d_in[19];
    const float* Wr1_ui = (const float*)d_in[20];
    const float* Wl1_iu = (const float*)d_in[21];
    const float* bl1_iu = (const float*)d_in[22];
    const float* Wr1_iu = (const float*)d_in[23];
    const float* g1_u   = (const float*)d_in[24];
    const float* b1_u   = (const float*)d_in[25];
    const float* g1_i   = (const float*)d_in[26];
    const float* b1_i   = (const float*)d_in[27];

    float* out = (float*)d_out;
    float* out_u = out;
    float* out_i = out + (size_t)NUSER * 64;

    float *hu, *hi, *Mu, *Qu, *Mi, *Qi;
    int *deg_u, *deg_i, *cur_u, *cur_i, *ptr_u, *ptr_i, *col_u, *col_i;
    cudaGetSymbolAddress((void**)&hu, g_hu);
    cudaGetSymbolAddress((void**)&hi, g_hi);
    cudaGetSymbolAddress((void**)&Mu, g_Mu);
    cudaGetSymbolAddress((void**)&Qu, g_Qu);
    cudaGetSymbolAddress((void**)&Mi, g_Mi);
    cudaGetSymbolAddress((void**)&Qi, g_Qi);
    cudaGetSymbolAddress((void**)&deg_u, g_deg_u);
    cudaGetSymbolAddress((void**)&deg_i, g_deg_i);
    cudaGetSymbolAddress((void**)&cur_u, g_cur_u);
    cudaGetSymbolAddress((void**)&cur_i, g_cur_i);
    cudaGetSymbolAddress((void**)&ptr_u, g_ptr_u);
    cudaGetSymbolAddress((void**)&ptr_i, g_ptr_i);
    cudaGetSymbolAddress((void**)&col_u, g_col_u);
    cudaGetSymbolAddress((void**)&col_i, g_col_i);

    const int eg  = (NEDGE + 255) / 256;
    const int zg  = (NUSER + 255) / 256;
    const int gm  = (NUSER + 127) / 128;   // == items grid (same count)
    const int ag  = (NUSER * 32 + 255) / 256;

    // ---- CSR build (per direction, reused by both layers) ----
    zero4_kernel<<<zg, 256>>>(deg_u, deg_i, cur_u, cur_i, NUSER);
    hist_kernel<<<eg, 256>>>(edge_ui, deg_i);   // dst = items
    hist_kernel<<<eg, 256>>>(edge_iu, deg_u);   // dst = users
    scan_kernel<<<1, 1024>>>(deg_i, ptr_i, NITEM);
    scan_kernel<<<1, 1024>>>(deg_u, ptr_u, NUSER);
    fill_kernel<<<eg, 256>>>(edge_ui, ptr_i, cur_i, col_i);
    fill_kernel<<<eg, 256>>>(edge_iu, ptr_u, cur_u, col_u);

    // ---- input projections + ReLU ----
    gemm_tf32_kernel<128, true><<<gm, 256>>>(x_user, Wp_u, bp_u, hu, NUSER, 96);
    gemm_tf32_kernel<128, true><<<gm, 256>>>(x_item, Wp_i, bp_i, hi, NITEM, 160);

    // ---- layer 0: source-side GEMMs (linearity: seg_mean(h)@W == seg_mean(h@W)) ----
    gemm_tf32_kernel<128, false><<<gm, 256>>>(hu, Wl0_ui, nullptr, Mu, NUSER, 128);
    gemm_tf32_kernel<128, false><<<gm, 256>>>(hu, Wr0_iu, nullptr, Qu, NUSER, 128);
    gemm_tf32_kernel<128, false><<<gm, 256>>>(hi, Wl0_iu, nullptr, Mi, NITEM, 128);
    gemm_tf32_kernel<128, false><<<gm, 256>>>(hi, Wr0_ui, nullptr, Qi, NITEM, 128);

    // h_i1 = relu(LN(mean_{ui}(Mu) + Qi + bl0_ui));  h_u1 = relu(LN(mean_{iu}(Mi) + Qu + bl0_iu))
    aggfin_kernel<4, true><<<ag, 256>>>(Mu, Qi, ptr_i, col_i, bl0_ui, g0_i, b0_i, hi, NITEM);
    aggfin_kernel<4, true><<<ag, 256>>>(Mi, Qu, ptr_u, col_u, bl0_iu, g0_u, b0_u, hu, NUSER);

    // ---- layer 1: source-side GEMMs (N=64), aggregate in 64-d ----
    gemm_tf32_kernel<64, false><<<gm, 256>>>(hu, Wl1_ui, nullptr, Mu, NUSER, 128);  // P_u
    gemm_tf32_kernel<64, false><<<gm, 256>>>(hu, Wr1_iu, nullptr, Qu, NUSER, 128);  // R_u
    gemm_tf32_kernel<64, false><<<gm, 256>>>(hi, Wl1_iu, nullptr, Mi, NITEM, 128);  // P_i
    gemm_tf32_kernel<64, false><<<gm, 256>>>(hi, Wr1_ui, nullptr, Qi, NITEM, 128);  // R_i

    // out_i = LN(mean_{ui}(P_u) + R_i + bl1_ui);  out_u = LN(mean_{iu}(P_i) + R_u + bl1_iu)
    aggfin_kernel<2, false><<<ag, 256>>>(Mu, Qi, ptr_i, col_i, bl1_ui, g1_i, b1_i, out_i, NITEM);
    aggfin_kernel<2, false><<<ag, 256>>>(Mi, Qu, ptr_u, col_u, bl1_iu, g1_u, b1_u, out_u, NUSER);
}

// round 6
// speedup vs baseline: 2.9958x; 1.3087x over previous
#include <cuda_runtime.h>
#include <cstddef>

#define NUSER 100000
#define NITEM 100000
#define NEDGE 600000
#define NTOT  (NUSER + NITEM)
#define HDIM  128
#define LN_EPS 1e-5f

// ---------------- scratch (device globals; no allocation allowed) ----------------
__device__ __align__(128) float g_hu [(size_t)NUSER * HDIM];   // h_u, then h_u1
__device__ __align__(128) float g_hi [(size_t)NITEM * HDIM];   // h_i, then h_i1
__device__ __align__(128) float g_Mu [(size_t)NUSER * HDIM];   // h_u@Wl0_ui   / P_u (64)
__device__ __align__(128) float g_Qu [(size_t)NUSER * HDIM];   // h_u@Wr0_iu   / R_u (64)
__device__ __align__(128) float g_Mi [(size_t)NITEM * HDIM];   // h_i@Wl0_iu   / P_i (64)
__device__ __align__(128) float g_Qi [(size_t)NITEM * HDIM];   // h_i@Wr0_ui   / R_i (64)

// combined CSR: users occupy deg/ptr slots [0,NUSER), items [NUSER,NTOT)
// col slots: users' adjacency in [0,NEDGE) region boundary implied by scan (sum deg_u == NEDGE)
__device__ int g_deg[NTOT];
__device__ int g_cur[NTOT];
__device__ int g_ptr[NTOT + 1];
__device__ int g_col[2 * NEDGE];
__device__ int g_bsum[256];
__device__ int g_boff[256];

#define SCAN_BLK 196           // ceil(NTOT / 1024)

// ---------------- small helpers ----------------
__device__ __forceinline__ unsigned f2tf(float x) {
    unsigned r;
    asm("cvt.rna.tf32.f32 %0, %1;" : "=r"(r) : "f"(x));
    return r;
}

__device__ __forceinline__ void mma8(float* c, const unsigned* a, const unsigned* b) {
    asm volatile(
        "mma.sync.aligned.m16n8k8.row.col.f32.tf32.tf32.f32 "
        "{%0,%1,%2,%3}, {%4,%5,%6,%7}, {%8,%9}, {%0,%1,%2,%3};"
        : "+f"(c[0]), "+f"(c[1]), "+f"(c[2]), "+f"(c[3])
        : "r"(a[0]), "r"(a[1]), "r"(a[2]), "r"(a[3]), "r"(b[0]), "r"(b[1]));
}

// ---------------- CSR build ----------------
__global__ void zero_kernel(int* __restrict__ deg, int* __restrict__ cur) {
    int i = blockIdx.x * blockDim.x + threadIdx.x;
    if (i < NTOT) { deg[i] = 0; cur[i] = 0; }
}

// both edge directions in one pass: i<NEDGE -> edge_iu (dst users), else edge_ui (dst items)
__global__ void hist_kernel(const int* __restrict__ edge_ui, const int* __restrict__ edge_iu,
                            int* __restrict__ deg) {
    int i = blockIdx.x * blockDim.x + threadIdx.x;
    if (i < NEDGE) {
        atomicAdd(&deg[__ldg(edge_iu + NEDGE + i)], 1);
    } else if (i < 2 * NEDGE) {
        atomicAdd(&deg[NUSER + __ldg(edge_ui + NEDGE + (i - NEDGE))], 1);
    }
}

// phase 1: per-block (1024 elems) sums
__global__ void scan1_kernel(const int* __restrict__ deg, int* __restrict__ bsum) {
    __shared__ int s[8];
    int b = blockIdx.x;
    int base = b * 1024 + threadIdx.x * 4;
    int sum = 0;
    if (base + 3 < NTOT) {
        int4 v = *reinterpret_cast<const int4*>(deg + base);
        sum = v.x + v.y + v.z + v.w;
    } else {
        for (int j = 0; j < 4; j++) if (base + j < NTOT) sum += deg[base + j];
    }
    #pragma unroll
    for (int o = 16; o; o >>= 1) sum += __shfl_xor_sync(0xffffffffu, sum, o);
    if ((threadIdx.x & 31) == 0) s[threadIdx.x >> 5] = sum;
    __syncthreads();
    if (threadIdx.x == 0) {
        int t = 0;
        #pragma unroll
        for (int j = 0; j < 8; j++) t += s[j];
        bsum[b] = t;
    }
}

// phase 2: exclusive scan of block sums (single warp-friendly block)
__global__ void scan2_kernel(const int* __restrict__ bsum, int* __restrict__ boff,
                             int* __restrict__ ptr) {
    __shared__ int s[256];
    int t = threadIdx.x;
    int v = (t < SCAN_BLK) ? bsum[t] : 0;
    s[t] = v;
    __syncthreads();
    for (int off = 1; off < 256; off <<= 1) {
        int u = (t >= off) ? s[t - off] : 0;
        __syncthreads();
        s[t] += u;
        __syncthreads();
    }
    if (t < SCAN_BLK) boff[t] = s[t] - v;
    if (t == 0) ptr[NTOT] = 2 * NEDGE;
}

// phase 3: per-block local exclusive scan + global offset -> ptr
__global__ void scan3_kernel(const int* __restrict__ deg, const int* __restrict__ boff,
                             int* __restrict__ ptr) {
    __shared__ int ws[8];
    int b = blockIdx.x;
    int t = threadIdx.x;
    int lane = t & 31, w = t >> 5;
    int base = b * 1024 + t * 4;

    int d[4];
    #pragma unroll
    for (int j = 0; j < 4; j++) d[j] = (base + j < NTOT) ? deg[base + j] : 0;
    int tsum = d[0] + d[1] + d[2] + d[3];

    // warp inclusive scan of tsum
    int incl = tsum;
    #pragma unroll
    for (int o = 1; o < 32; o <<= 1) {
        int u = __shfl_up_sync(0xffffffffu, incl, o);
        if (lane >= o) incl += u;
    }
    if (lane == 31) ws[w] = incl;
    __syncthreads();
    int wexcl = 0;
    #pragma unroll
    for (int j = 0; j < 8; j++) wexcl += (j < w) ? ws[j] : 0;
    int run = boff[b] + wexcl + (incl - tsum);
    #pragma unroll
    for (int j = 0; j < 4; j++) {
        if (base + j < NTOT) ptr[base + j] = run;
        run += d[j];
    }
}

__global__ void fill_kernel(const int* __restrict__ edge_ui, const int* __restrict__ edge_iu,
                            const int* __restrict__ ptr, int* __restrict__ cur,
                            int* __restrict__ col) {
    int i = blockIdx.x * blockDim.x + threadIdx.x;
    if (i < NEDGE) {
        int d = __ldg(edge_iu + NEDGE + i);
        int p = atomicAdd(&cur[d], 1);
        col[__ldg(ptr + d) + p] = __ldg(edge_iu + i);
    } else if (i < 2 * NEDGE) {
        int e = i - NEDGE;
        int d = NUSER + __ldg(edge_ui + NEDGE + e);
        int p = atomicAdd(&cur[d], 1);
        col[__ldg(ptr + d) + p] = __ldg(edge_ui + e);
    }
}

// ---------------- TF32 tensor-core GEMM: C[M,BN] = A[M,K] @ W[K,BN] (+bias,ReLU) ----------------
template<int BN, bool BIASRELU>
__launch_bounds__(256, 2)
__global__ void gemm_tf32_kernel(const float* __restrict__ A, const float* __restrict__ W,
                                 const float* __restrict__ bias, float* __restrict__ C,
                                 int M, int K)
{
    constexpr int WM = (BN == 128) ? 64 : 32;
    constexpr int WARPS_N = BN / 32;
    constexpr int MT = WM / 16;
    constexpr int NT = 4;

    __shared__ unsigned As[128][36];
    __shared__ unsigned Bs[32][BN + 8];

    const int t = threadIdx.x;
    const int w = t >> 5, lane = t & 31;
    const int g = lane >> 2, tg = lane & 3;
    const int wm = w / WARPS_N, wn = w % WARPS_N;
    const int m0 = blockIdx.x * 128;

    float acc[MT][NT][4];
    #pragma unroll
    for (int mt = 0; mt < MT; mt++)
        #pragma unroll
        for (int nt = 0; nt < NT; nt++)
            #pragma unroll
            for (int j = 0; j < 4; j++) acc[mt][nt][j] = 0.f;

    for (int kc = 0; kc < K; kc += 32) {
        #pragma unroll
        for (int q = 0; q < 4; q++) {
            int idx = t * 4 + q;
            int row = idx >> 3;
            int kq = (idx & 7) * 4;
            float4 v = make_float4(0.f, 0.f, 0.f, 0.f);
            if (m0 + row < M)
                v = *reinterpret_cast<const float4*>(A + (size_t)(m0 + row) * K + kc + kq);
            As[row][kq + 0] = f2tf(v.x);
            As[row][kq + 1] = f2tf(v.y);
            As[row][kq + 2] = f2tf(v.z);
            As[row][kq + 3] = f2tf(v.w);
        }
        constexpr int WF4 = 32 * BN / 4;
        #pragma unroll
        for (int i = t; i < WF4; i += 256) {
            int k = i / (BN / 4);
            int n4 = (i % (BN / 4)) * 4;
            float4 v = *reinterpret_cast<const float4*>(W + (size_t)(kc + k) * BN + n4);
            Bs[k][n4 + 0] = f2tf(v.x);
            Bs[k][n4 + 1] = f2tf(v.y);
            Bs[k][n4 + 2] = f2tf(v.z);
            Bs[k][n4 + 3] = f2tf(v.w);
        }
        __syncthreads();

        #pragma unroll
        for (int kk = 0; kk < 32; kk += 8) {
            unsigned a[MT][4], b[NT][2];
            #pragma unroll
            for (int mt = 0; mt < MT; mt++) {
                int r = wm * WM + mt * 16 + g;
                a[mt][0] = As[r][kk + tg];
                a[mt][1] = As[r + 8][kk + tg];
                a[mt][2] = As[r][kk + tg + 4];
                a[mt][3] = As[r + 8][kk + tg + 4];
            }
            #pragma unroll
            for (int nt = 0; nt < NT; nt++) {
                int c = wn * 32 + nt * 8 + g;
                b[nt][0] = Bs[kk + tg][c];
                b[nt][1] = Bs[kk + tg + 4][c];
            }
            #pragma unroll
            for (int mt = 0; mt < MT; mt++)
                #pragma unroll
                for (int nt = 0; nt < NT; nt++)
                    mma8(acc[mt][nt], a[mt], b[nt]);
        }
        __syncthreads();
    }

    #pragma unroll
    for (int mt = 0; mt < MT; mt++) {
        int r0 = m0 + wm * WM + mt * 16 + g;
        #pragma unroll
        for (int nt = 0; nt < NT; nt++) {
            int c = wn * 32 + nt * 8 + 2 * tg;
            float x0 = acc[mt][nt][0], x1 = acc[mt][nt][1];
            float x2 = acc[mt][nt][2], x3 = acc[mt][nt][3];
            if (BIASRELU) {
                float b0 = __ldg(bias + c), b1 = __ldg(bias + c + 1);
                x0 = fmaxf(x0 + b0, 0.f); x1 = fmaxf(x1 + b1, 0.f);
                x2 = fmaxf(x2 + b0, 0.f); x3 = fmaxf(x3 + b1, 0.f);
            }
            if (r0 < M)
                *reinterpret_cast<float2*>(C + (size_t)r0 * BN + c) = make_float2(x0, x1);
            if (r0 + 8 < M)
                *reinterpret_cast<float2*>(C + (size_t)(r0 + 8) * BN + c) = make_float2(x2, x3);
        }
    }
}

// ---------------- fused CSR gather-mean + self + bias + LN (+ReLU) ----------------
template<int VPL, bool RELU>
__global__ void aggfin_kernel(const float* __restrict__ msg, const float* __restrict__ self,
                              const int* __restrict__ ptr, const int* __restrict__ col,
                              const float* __restrict__ bias,
                              const float* __restrict__ gamma, const float* __restrict__ beta,
                              float* __restrict__ out, int n)
{
    constexpr int C = 32 * VPL;
    int gw = (blockIdx.x * blockDim.x + threadIdx.x) >> 5;
    if (gw >= n) return;
    int lane = threadIdx.x & 31;

    int p0 = __ldg(ptr + gw), p1 = __ldg(ptr + gw + 1);
    float v[VPL];
    #pragma unroll
    for (int j = 0; j < VPL; j++) v[j] = 0.f;

    for (int e = p0; e < p1; e++) {
        int s = __ldg(col + e);
        const float* mp = msg + (size_t)s * C + lane * VPL;
        if (VPL == 4) {
            float4 t4 = *reinterpret_cast<const float4*>(mp);
            v[0] += t4.x; v[1] += t4.y; v[2 % VPL] += t4.z; v[3 % VPL] += t4.w;
        } else {
            float2 t2 = *reinterpret_cast<const float2*>(mp);
            v[0] += t2.x; v[1 % VPL] += t2.y;
        }
    }
    float inv = 1.f / fmaxf((float)(p1 - p0), 1.f);

    const float* sp = self + (size_t)gw * C + lane * VPL;
    if (VPL == 4) {
        float4 s4 = *reinterpret_cast<const float4*>(sp);
        v[0] = v[0] * inv + s4.x; v[1] = v[1] * inv + s4.y;
        v[2 % VPL] = v[2 % VPL] * inv + s4.z; v[3 % VPL] = v[3 % VPL] * inv + s4.w;
    } else {
        float2 s2 = *reinterpret_cast<const float2*>(sp);
        v[0] = v[0] * inv + s2.x; v[1 % VPL] = v[1 % VPL] * inv + s2.y;
    }
    #pragma unroll
    for (int j = 0; j < VPL; j++) v[j] += __ldg(bias + lane * VPL + j);

    float s = 0.f;
    #pragma unroll
    for (int j = 0; j < VPL; j++) s += v[j];
    #pragma unroll
    for (int o = 16; o > 0; o >>= 1) s += __shfl_xor_sync(0xffffffffu, s, o);
    float mean = s * (1.f / C);
    float q = 0.f;
    #pragma unroll
    for (int j = 0; j < VPL; j++) { float d = v[j] - mean; q += d * d; }
    #pragma unroll
    for (int o = 16; o > 0; o >>= 1) q += __shfl_xor_sync(0xffffffffu, q, o);
    float rstd = rsqrtf(q * (1.f / C) + LN_EPS);

    float* op = out + (size_t)gw * C + lane * VPL;
    float ov[VPL];
    #pragma unroll
    for (int j = 0; j < VPL; j++) {
        float x = (v[j] - mean) * rstd * __ldg(gamma + lane * VPL + j) + __ldg(beta + lane * VPL + j);
        ov[j] = RELU ? fmaxf(x, 0.f) : x;
    }
    if (VPL == 4)
        *reinterpret_cast<float4*>(op) = make_float4(ov[0], ov[1], ov[2 % VPL], ov[3 % VPL]);
    else
        *reinterpret_cast<float2*>(op) = make_float2(ov[0], ov[1 % VPL]);
}

// ---------------- host ----------------
extern "C" void kernel_launch(void* const* d_in, const int* in_sizes, int n_in,
                              void* d_out, int out_size) {
    (void)in_sizes; (void)n_in; (void)out_size;

    const float* x_user  = (const float*)d_in[0];
    const float* x_item  = (const float*)d_in[1];
    const int*   edge_ui = (const int*)d_in[2];
    const int*   edge_iu = (const int*)d_in[3];
    const float* Wp_u   = (const float*)d_in[4];
    const float* bp_u   = (const float*)d_in[5];
    const float* Wp_i   = (const float*)d_in[6];
    const float* bp_i   = (const float*)d_in[7];
    const float* Wl0_ui = (const float*)d_in[8];
    const float* bl0_ui = (const float*)d_in[9];
    const float* Wr0_ui = (const float*)d_in[10];
    const float* Wl0_iu = (const float*)d_in[11];
    const float* bl0_iu = (const float*)d_in[12];
    const float* Wr0_iu = (const float*)d_in[13];
    const float* g0_u   = (const float*)d_in[14];
    const float* b0_u   = (const float*)d_in[15];
    const float* g0_i   = (const float*)d_in[16];
    const float* b0_i   = (const float*)d_in[17];
    const float* Wl1_ui = (const float*)d_in[18];
    const float* bl1_ui = (const float*)d_in[19];
    const float* Wr1_ui = (const float*)d_in[20];
    const float* Wl1_iu = (const float*)d_in[21];
    const float* bl1_iu = (const float*)d_in[22];
    const float* Wr1_iu = (const float*)d_in[23];
    const float* g1_u   = (const float*)d_in[24];
    const float* b1_u   = (const float*)d_in[25];
    const float* g1_i   = (const float*)d_in[26];
    const float* b1_i   = (const float*)d_in[27];

    float* out = (float*)d_out;
    float* out_u = out;
    float* out_i = out + (size_t)NUSER * 64;

    float *hu, *hi, *Mu, *Qu, *Mi, *Qi;
    int *deg, *cur, *ptr, *col, *bsum, *boff;
    cudaGetSymbolAddress((void**)&hu, g_hu);
    cudaGetSymbolAddress((void**)&hi, g_hi);
    cudaGetSymbolAddress((void**)&Mu, g_Mu);
    cudaGetSymbolAddress((void**)&Qu, g_Qu);
    cudaGetSymbolAddress((void**)&Mi, g_Mi);
    cudaGetSymbolAddress((void**)&Qi, g_Qi);
    cudaGetSymbolAddress((void**)&deg, g_deg);
    cudaGetSymbolAddress((void**)&cur, g_cur);
    cudaGetSymbolAddress((void**)&ptr, g_ptr);
    cudaGetSymbolAddress((void**)&col, g_col);
    cudaGetSymbolAddress((void**)&bsum, g_bsum);
    cudaGetSymbolAddress((void**)&boff, g_boff);

    const int* ptr_u = ptr;              // users: slots [0, NUSER)
    const int* ptr_i = ptr + NUSER;      // items: slots [NUSER, NTOT)

    const int e2g = (2 * NEDGE + 255) / 256;
    const int zg  = (NTOT + 255) / 256;
    const int gm  = (NUSER + 127) / 128;
    const int ag  = (NUSER * 32 + 255) / 256;

    // ---- CSR build (combined directions; multi-block scan) ----
    zero_kernel<<<zg, 256>>>(deg, cur);
    hist_kernel<<<e2g, 256>>>(edge_ui, edge_iu, deg);
    scan1_kernel<<<SCAN_BLK, 256>>>(deg, bsum);
    scan2_kernel<<<1, 256>>>(bsum, boff, ptr);
    scan3_kernel<<<SCAN_BLK, 256>>>(deg, boff, ptr);
    fill_kernel<<<e2g, 256>>>(edge_ui, edge_iu, ptr, cur, col);

    // ---- input projections + ReLU ----
    gemm_tf32_kernel<128, true><<<gm, 256>>>(x_user, Wp_u, bp_u, hu, NUSER, 96);
    gemm_tf32_kernel<128, true><<<gm, 256>>>(x_item, Wp_i, bp_i, hi, NITEM, 160);

    // ---- layer 0: source-side GEMMs ----
    gemm_tf32_kernel<128, false><<<gm, 256>>>(hu, Wl0_ui, nullptr, Mu, NUSER, 128);
    gemm_tf32_kernel<128, false><<<gm, 256>>>(hu, Wr0_iu, nullptr, Qu, NUSER, 128);
    gemm_tf32_kernel<128, false><<<gm, 256>>>(hi, Wl0_iu, nullptr, Mi, NITEM, 128);
    gemm_tf32_kernel<128, false><<<gm, 256>>>(hi, Wr0_ui, nullptr, Qi, NITEM, 128);

    aggfin_kernel<4, true><<<ag, 256>>>(Mu, Qi, ptr_i, col, bl0_ui, g0_i, b0_i, hi, NITEM);
    aggfin_kernel<4, true><<<ag, 256>>>(Mi, Qu, ptr_u, col, bl0_iu, g0_u, b0_u, hu, NUSER);

    // ---- layer 1: source-side GEMMs (N=64) ----
    gemm_tf32_kernel<64, false><<<gm, 256>>>(hu, Wl1_ui, nullptr, Mu, NUSER, 128);
    gemm_tf32_kernel<64, false><<<gm, 256>>>(hu, Wr1_iu, nullptr, Qu, NUSER, 128);
    gemm_tf32_kernel<64, false><<<gm, 256>>>(hi, Wl1_iu, nullptr, Mi, NITEM, 128);
    gemm_tf32_kernel<64, false><<<gm, 256>>>(hi, Wr1_ui, nullptr, Qi, NITEM, 128);

    aggfin_kernel<2, false><<<ag, 256>>>(Mu, Qi, ptr_i, col, bl1_ui, g1_i, b1_i, out_i, NITEM);
    aggfin_kernel<2, false><<<ag, 256>>>(Mi, Qu, ptr_u, col, bl1_iu, g1_u, b1_u, out_u, NUSER);
}

// round 11
// speedup vs baseline: 3.6825x; 1.2292x over previous
#include <cuda_runtime.h>
#include <cstddef>
#include <cstdint>

#define NUSER 100000
#define NITEM 100000
#define NEDGE 600000
#define NTOT  (NUSER + NITEM)
#define HDIM  128
#define LN_EPS 1e-5f

// ---------------- scratch (device globals; no allocation allowed) ----------------
__device__ __align__(128) float g_hu [(size_t)NUSER * HDIM];
__device__ __align__(128) float g_hi [(size_t)NITEM * HDIM];
__device__ __align__(128) float g_Mu [(size_t)NUSER * HDIM];
__device__ __align__(128) float g_Qu [(size_t)NUSER * HDIM];
__device__ __align__(128) float g_Mi [(size_t)NITEM * HDIM];
__device__ __align__(128) float g_Qi [(size_t)NITEM * HDIM];

__device__ int g_deg[NTOT];
__device__ int g_cur[NTOT];
__device__ int g_ptr[NTOT + 1];
__device__ int g_col[2 * NEDGE];
__device__ int g_bsum[256];
__device__ int g_boff[256];

#define SCAN_BLK 196

// ---------------- small helpers ----------------
__device__ __forceinline__ unsigned f2tf(float x) {
    unsigned r;
    asm("cvt.rna.tf32.f32 %0, %1;" : "=r"(r) : "f"(x));
    return r;
}
__device__ __forceinline__ void mma8(float* c, const unsigned* a, const unsigned* b) {
    asm volatile(
        "mma.sync.aligned.m16n8k8.row.col.f32.tf32.tf32.f32 "
        "{%0,%1,%2,%3}, {%4,%5,%6,%7}, {%8,%9}, {%0,%1,%2,%3};"
        : "+f"(c[0]), "+f"(c[1]), "+f"(c[2]), "+f"(c[3])
        : "r"(a[0]), "r"(a[1]), "r"(a[2]), "r"(a[3]), "r"(b[0]), "r"(b[1]));
}
__device__ __forceinline__ uint32_t smem_u32(const void* p) {
    uint32_t a;
    asm("{ .reg .u64 t; cvta.to.shared.u64 t, %1; cvt.u32.u64 %0, t; }" : "=r"(a) : "l"(p));
    return a;
}
__device__ __forceinline__ void cpa16(uint32_t dst, const void* src, int src_sz) {
    asm volatile("cp.async.cg.shared.global [%0], [%1], 16, %2;"
                 :: "r"(dst), "l"(src), "r"(src_sz));
}
__device__ __forceinline__ void cpa_commit() {
    asm volatile("cp.async.commit_group;" ::: "memory");
}
template<int N>
__device__ __forceinline__ void cpa_wait() {
    asm volatile("cp.async.wait_group %0;" :: "n"(N) : "memory");
}

// ---------------- CSR build ----------------
__global__ void zero_kernel(int* __restrict__ deg, int* __restrict__ cur) {
    int i = blockIdx.x * blockDim.x + threadIdx.x;
    if (i < NTOT) { deg[i] = 0; cur[i] = 0; }
}

__global__ void hist_kernel(const int* __restrict__ edge_ui, const int* __restrict__ edge_iu,
                            int* __restrict__ deg) {
    int i = blockIdx.x * blockDim.x + threadIdx.x;
    if (i < NEDGE) {
        atomicAdd(&deg[__ldg(edge_iu + NEDGE + i)], 1);
    } else if (i < 2 * NEDGE) {
        atomicAdd(&deg[NUSER + __ldg(edge_ui + NEDGE + (i - NEDGE))], 1);
    }
}

__global__ void scan1_kernel(const int* __restrict__ deg, int* __restrict__ bsum) {
    __shared__ int s[8];
    int b = blockIdx.x;
    int base = b * 1024 + threadIdx.x * 4;
    int sum = 0;
    if (base + 3 < NTOT) {
        int4 v = *reinterpret_cast<const int4*>(deg + base);
        sum = v.x + v.y + v.z + v.w;
    } else {
        for (int j = 0; j < 4; j++) if (base + j < NTOT) sum += deg[base + j];
    }
    #pragma unroll
    for (int o = 16; o; o >>= 1) sum += __shfl_xor_sync(0xffffffffu, sum, o);
    if ((threadIdx.x & 31) == 0) s[threadIdx.x >> 5] = sum;
    __syncthreads();
    if (threadIdx.x == 0) {
        int t = 0;
        #pragma unroll
        for (int j = 0; j < 8; j++) t += s[j];
        bsum[b] = t;
    }
}

__global__ void scan2_kernel(const int* __restrict__ bsum, int* __restrict__ boff,
                             int* __restrict__ ptr) {
    __shared__ int s[256];
    int t = threadIdx.x;
    int v = (t < SCAN_BLK) ? bsum[t] : 0;
    s[t] = v;
    __syncthreads();
    for (int off = 1; off < 256; off <<= 1) {
        int u = (t >= off) ? s[t - off] : 0;
        __syncthreads();
        s[t] += u;
        __syncthreads();
    }
    if (t < SCAN_BLK) boff[t] = s[t] - v;
    if (t == 0) ptr[NTOT] = 2 * NEDGE;
}

__global__ void scan3_kernel(const int* __restrict__ deg, const int* __restrict__ boff,
                             int* __restrict__ ptr) {
    __shared__ int ws[8];
    int b = blockIdx.x;
    int t = threadIdx.x;
    int lane = t & 31, w = t >> 5;
    int base = b * 1024 + t * 4;

    int d[4];
    #pragma unroll
    for (int j = 0; j < 4; j++) d[j] = (base + j < NTOT) ? deg[base + j] : 0;
    int tsum = d[0] + d[1] + d[2] + d[3];

    int incl = tsum;
    #pragma unroll
    for (int o = 1; o < 32; o <<= 1) {
        int u = __shfl_up_sync(0xffffffffu, incl, o);
        if (lane >= o) incl += u;
    }
    if (lane == 31) ws[w] = incl;
    __syncthreads();
    int wexcl = 0;
    #pragma unroll
    for (int j = 0; j < 8; j++) wexcl += (j < w) ? ws[j] : 0;
    int run = boff[b] + wexcl + (incl - tsum);
    #pragma unroll
    for (int j = 0; j < 4; j++) {
        if (base + j < NTOT) ptr[base + j] = run;
        run += d[j];
    }
}

__global__ void fill_kernel(const int* __restrict__ edge_ui, const int* __restrict__ edge_iu,
                            const int* __restrict__ ptr, int* __restrict__ cur,
                            int* __restrict__ col) {
    int i = blockIdx.x * blockDim.x + threadIdx.x;
    if (i < NEDGE) {
        int d = __ldg(edge_iu + NEDGE + i);
        int p = atomicAdd(&cur[d], 1);
        col[__ldg(ptr + d) + p] = __ldg(edge_iu + i);
    } else if (i < 2 * NEDGE) {
        int e = i - NEDGE;
        int d = NUSER + __ldg(edge_ui + NEDGE + e);
        int p = atomicAdd(&cur[d], 1);
        col[__ldg(ptr + d) + p] = __ldg(edge_ui + e);
    }
}

// ---------------- TF32 mma GEMM, cp.async 2-stage, concatenated N with split output --------
// C0[M,SPLIT] = A[M,K] @ W0[K,SPLIT]  (+bias,ReLU when BIASRELU)
// C1[M,BN-SPLIT] = A[M,K] @ W1[K,BN-SPLIT]            (only when SPLIT < BN)
// Tile: 128 x BN per CTA, 256 threads, 8 warps (2 in M x 4 in N), WM=64, WN=BN/4.
template<int BN, int SPLIT, bool BIASRELU>
__global__ void __launch_bounds__(256)
gemm_kernel(const float* __restrict__ A,
            const float* __restrict__ W0, const float* __restrict__ W1,
            const float* __restrict__ bias,
            float* __restrict__ C0, float* __restrict__ C1,
            int M, int K)
{
    constexpr int WN = BN / 4;
    constexpr int MT = 4;          // 64 / 16
    constexpr int NT = WN / 8;
    constexpr int BROW = BN + 8;   // Bs row stride (floats)
    constexpr int A_ST = 128 * 36; // floats per A stage
    constexpr int B_ST = 32 * BROW;
    constexpr int STG  = A_ST + B_ST;

    extern __shared__ float sm[];
    const uint32_t smb = smem_u32(sm);

    const int t = threadIdx.x;
    const int w = t >> 5, lane = t & 31;
    const int g = lane >> 2, tg = lane & 3;
    const int wm = w >> 2, wn = w & 3;
    const int m0 = blockIdx.x * 128;
    const int CH = K >> 5;

    float acc[MT][NT][4];
    #pragma unroll
    for (int mt = 0; mt < MT; mt++)
        #pragma unroll
        for (int nt = 0; nt < NT; nt++)
            #pragma unroll
            for (int j = 0; j < 4; j++) acc[mt][nt][j] = 0.f;

    // ---- async tile loaders ----
    auto loadA = [&](int c, int buf) {
        uint32_t base = smb + (uint32_t)(buf * STG) * 4u;
        #pragma unroll
        for (int q = 0; q < 4; q++) {
            int i = t + q * 256;          // 1024 16B-chunks
            int row = i >> 3, j = i & 7;
            bool val = (m0 + row) < M;
            const float* src = val ? (A + (size_t)(m0 + row) * K + c * 32 + j * 4) : A;
            cpa16(base + (uint32_t)(row * 36 + j * 4) * 4u, src, val ? 16 : 0);
        }
    };
    auto loadB = [&](int c, int buf) {
        uint32_t base = smb + (uint32_t)(buf * STG + A_ST) * 4u;
        #pragma unroll
        for (int i = t; i < 8 * BN; i += 256) {
            int k = i / (BN / 4);
            int ncol = (i % (BN / 4)) * 4;
            const float* src = (ncol < SPLIT)
                ? (W0 + (size_t)(c * 32 + k) * SPLIT + ncol)
                : (W1 + (size_t)(c * 32 + k) * (BN - SPLIT) + (ncol - SPLIT));
            cpa16(base + (uint32_t)(k * BROW + ncol) * 4u, src, 16);
        }
    };

    loadA(0, 0); loadB(0, 0); cpa_commit();

    for (int c = 0; c < CH; c++) {
        if (c + 1 < CH) {
            loadA(c + 1, (c + 1) & 1); loadB(c + 1, (c + 1) & 1); cpa_commit();
            cpa_wait<1>();
        } else {
            cpa_wait<0>();
        }
        __syncthreads();

        const float* As = sm + (c & 1) * STG;
        const float* Bs = As + A_ST;

        #pragma unroll
        for (int kk = 0; kk < 32; kk += 8) {
            unsigned a[MT][4], b[NT][2];
            #pragma unroll
            for (int mt = 0; mt < MT; mt++) {
                int r = wm * 64 + mt * 16 + g;
                a[mt][0] = f2tf(As[r * 36 + kk + tg]);
                a[mt][1] = f2tf(As[(r + 8) * 36 + kk + tg]);
                a[mt][2] = f2tf(As[r * 36 + kk + tg + 4]);
                a[mt][3] = f2tf(As[(r + 8) * 36 + kk + tg + 4]);
            }
            #pragma unroll
            for (int nt = 0; nt < NT; nt++) {
                int cc = wn * WN + nt * 8 + g;
                b[nt][0] = f2tf(Bs[(kk + tg) * BROW + cc]);
                b[nt][1] = f2tf(Bs[(kk + tg + 4) * BROW + cc]);
            }
            #pragma unroll
            for (int mt = 0; mt < MT; mt++)
                #pragma unroll
                for (int nt = 0; nt < NT; nt++)
                    mma8(acc[mt][nt], a[mt], b[nt]);
        }
        __syncthreads();
    }

    // ---- epilogue: split fragment stores ----
    #pragma unroll
    for (int mt = 0; mt < MT; mt++) {
        int r0 = m0 + wm * 64 + mt * 16 + g;
        #pragma unroll
        for (int nt = 0; nt < NT; nt++) {
            int c = wn * WN + nt * 8 + 2 * tg;
            float x0 = acc[mt][nt][0], x1 = acc[mt][nt][1];
            float x2 = acc[mt][nt][2], x3 = acc[mt][nt][3];
            if (BIASRELU) {
                float b0 = __ldg(bias + c), b1 = __ldg(bias + c + 1);
                x0 = fmaxf(x0 + b0, 0.f); x1 = fmaxf(x1 + b1, 0.f);
                x2 = fmaxf(x2 + b0, 0.f); x3 = fmaxf(x3 + b1, 0.f);
            }
            float* base; int stride, cc;
            if (c < SPLIT) { base = C0; stride = SPLIT; cc = c; }
            else           { base = C1; stride = BN - SPLIT; cc = c - SPLIT; }
            if (r0 < M)
                *reinterpret_cast<float2*>(base + (size_t)r0 * stride + cc) = make_float2(x0, x1);
            if (r0 + 8 < M)
                *reinterpret_cast<float2*>(base + (size_t)(r0 + 8) * stride + cc) = make_float2(x2, x3);
        }
    }
}

// ---------------- fused CSR gather-mean + self + bias + LN (+ReLU) ----------------
template<int VPL, bool RELU>
__global__ void aggfin_kernel(const float* __restrict__ msg, const float* __restrict__ self,
                              const int* __restrict__ ptr, const int* __restrict__ col,
                              const float* __restrict__ bias,
                              const float* __restrict__ gamma, const float* __restrict__ beta,
                              float* __restrict__ out, int n)
{
    constexpr int C = 32 * VPL;
    int gw = (blockIdx.x * blockDim.x + threadIdx.x) >> 5;
    if (gw >= n) return;
    int lane = threadIdx.x & 31;

    int p0 = __ldg(ptr + gw), p1 = __ldg(ptr + gw + 1);
    float v[VPL];
    #pragma unroll
    for (int j = 0; j < VPL; j++) v[j] = 0.f;

    for (int e = p0; e < p1; e++) {
        int s = __ldg(col + e);
        const float* mp = msg + (size_t)s * C + lane * VPL;
        if (VPL == 4) {
            float4 t4 = *reinterpret_cast<const float4*>(mp);
            v[0] += t4.x; v[1] += t4.y; v[2 % VPL] += t4.z; v[3 % VPL] += t4.w;
        } else {
            float2 t2 = *reinterpret_cast<const float2*>(mp);
            v[0] += t2.x; v[1 % VPL] += t2.y;
        }
    }
    float inv = 1.f / fmaxf((float)(p1 - p0), 1.f);

    const float* sp = self + (size_t)gw * C + lane * VPL;
    if (VPL == 4) {
        float4 s4 = *reinterpret_cast<const float4*>(sp);
        v[0] = v[0] * inv + s4.x; v[1] = v[1] * inv + s4.y;
        v[2 % VPL] = v[2 % VPL] * inv + s4.z; v[3 % VPL] = v[3 % VPL] * inv + s4.w;
    } else {
        float2 s2 = *reinterpret_cast<const float2*>(sp);
        v[0] = v[0] * inv + s2.x; v[1 % VPL] = v[1 % VPL] * inv + s2.y;
    }
    #pragma unroll
    for (int j = 0; j < VPL; j++) v[j] += __ldg(bias + lane * VPL + j);

    float s = 0.f;
    #pragma unroll
    for (int j = 0; j < VPL; j++) s += v[j];
    #pragma unroll
    for (int o = 16; o > 0; o >>= 1) s += __shfl_xor_sync(0xffffffffu, s, o);
    float mean = s * (1.f / C);
    float q = 0.f;
    #pragma unroll
    for (int j = 0; j < VPL; j++) { float d = v[j] - mean; q += d * d; }
    #pragma unroll
    for (int o = 16; o > 0; o >>= 1) q += __shfl_xor_sync(0xffffffffu, q, o);
    float rstd = rsqrtf(q * (1.f / C) + LN_EPS);

    float* op = out + (size_t)gw * C + lane * VPL;
    float ov[VPL];
    #pragma unroll
    for (int j = 0; j < VPL; j++) {
        float x = (v[j] - mean) * rstd * __ldg(gamma + lane * VPL + j) + __ldg(beta + lane * VPL + j);
        ov[j] = RELU ? fmaxf(x, 0.f) : x;
    }
    if (VPL == 4)
        *reinterpret_cast<float4*>(op) = make_float4(ov[0], ov[1], ov[2 % VPL], ov[3 % VPL]);
    else
        *reinterpret_cast<float2*>(op) = make_float2(ov[0], ov[1 % VPL]);
}

// ---------------- host ----------------
extern "C" void kernel_launch(void* const* d_in, const int* in_sizes, int n_in,
                              void* d_out, int out_size) {
    (void)in_sizes; (void)n_in; (void)out_size;

    const float* x_user  = (const float*)d_in[0];
    const float* x_item  = (const float*)d_in[1];
    const int*   edge_ui = (const int*)d_in[2];
    const int*   edge_iu = (const int*)d_in[3];
    const float* Wp_u   = (const float*)d_in[4];
    const float* bp_u   = (const float*)d_in[5];
    const float* Wp_i   = (const float*)d_in[6];
    const float* bp_i   = (const float*)d_in[7];
    const float* Wl0_ui = (const float*)d_in[8];
    const float* bl0_ui = (const float*)d_in[9];
    const float* Wr0_ui = (const float*)d_in[10];
    const float* Wl0_iu = (const float*)d_in[11];
    const float* bl0_iu = (const float*)d_in[12];
    const float* Wr0_iu = (const float*)d_in[13];
    const float* g0_u   = (const float*)d_in[14];
    const float* b0_u   = (const float*)d_in[15];
    const float* g0_i   = (const float*)d_in[16];
    const float* b0_i   = (const float*)d_in[17];
    const float* Wl1_ui = (const float*)d_in[18];
    const float* bl1_ui = (const float*)d_in[19];
    const float* Wr1_ui = (const float*)d_in[20];
    const float* Wl1_iu = (const float*)d_in[21];
    const float* bl1_iu = (const float*)d_in[22];
    const float* Wr1_iu = (const float*)d_in[23];
    const float* g1_u   = (const float*)d_in[24];
    const float* b1_u   = (const float*)d_in[25];
    const float* g1_i   = (const float*)d_in[26];
    const float* b1_i   = (const float*)d_in[27];

    float* out = (float*)d_out;
    float* out_u = out;
    float* out_i = out + (size_t)NUSER * 64;

    float *hu, *hi, *Mu, *Qu, *Mi, *Qi;
    int *deg, *cur, *ptr, *col, *bsum, *boff;
    cudaGetSymbolAddress((void**)&hu, g_hu);
    cudaGetSymbolAddress((void**)&hi, g_hi);
    cudaGetSymbolAddress((void**)&Mu, g_Mu);
    cudaGetSymbolAddress((void**)&Qu, g_Qu);
    cudaGetSymbolAddress((void**)&Mi, g_Mi);
    cudaGetSymbolAddress((void**)&Qi, g_Qi);
    cudaGetSymbolAddress((void**)&deg, g_deg);
    cudaGetSymbolAddress((void**)&cur, g_cur);
    cudaGetSymbolAddress((void**)&ptr, g_ptr);
    cudaGetSymbolAddress((void**)&col, g_col);
    cudaGetSymbolAddress((void**)&bsum, g_bsum);
    cudaGetSymbolAddress((void**)&boff, g_boff);

    const int* ptr_u = ptr;
    const int* ptr_i = ptr + NUSER;

    // dynamic smem: 2 stages of (A: 128*36 + B: 32*(BN+8)) floats
    const int smem128 = 2 * (128 * 36 + 32 * (128 + 8)) * 4;   //  71680 B
    const int smem256 = 2 * (128 * 36 + 32 * (256 + 8)) * 4;   // 104448 B
    cudaFuncSetAttribute(gemm_kernel<128, 128, true>,  cudaFuncAttributeMaxDynamicSharedMemorySize, smem128);
    cudaFuncSetAttribute(gemm_kernel<256, 128, false>, cudaFuncAttributeMaxDynamicSharedMemorySize, smem256);
    cudaFuncSetAttribute(gemm_kernel<128, 64,  false>, cudaFuncAttributeMaxDynamicSharedMemorySize, smem128);

    const int e2g = (2 * NEDGE + 255) / 256;
    const int zg  = (NTOT + 255) / 256;
    const int gm  = (NUSER + 127) / 128;
    const int ag  = (NUSER * 32 + 255) / 256;

    // ---- CSR build ----
    zero_kernel<<<zg, 256>>>(deg, cur);
    hist_kernel<<<e2g, 256>>>(edge_ui, edge_iu, deg);
    scan1_kernel<<<SCAN_BLK, 256>>>(deg, bsum);
    scan2_kernel<<<1, 256>>>(bsum, boff, ptr);
    scan3_kernel<<<SCAN_BLK, 256>>>(deg, boff, ptr);
    fill_kernel<<<e2g, 256>>>(edge_ui, edge_iu, ptr, cur, col);

    // ---- input projections + ReLU ----
    gemm_kernel<128, 128, true><<<gm, 256, smem128>>>(x_user, Wp_u, Wp_u, bp_u, hu, hu, NUSER, 96);
    gemm_kernel<128, 128, true><<<gm, 256, smem128>>>(x_item, Wp_i, Wp_i, bp_i, hi, hi, NITEM, 160);

    // ---- layer 0: concatenated source-side GEMMs (N=256, split 128/128) ----
    gemm_kernel<256, 128, false><<<gm, 256, smem256>>>(hu, Wl0_ui, Wr0_iu, nullptr, Mu, Qu, NUSER, 128);
    gemm_kernel<256, 128, false><<<gm, 256, smem256>>>(hi, Wl0_iu, Wr0_ui, nullptr, Mi, Qi, NITEM, 128);

    aggfin_kernel<4, true><<<ag, 256>>>(Mu, Qi, ptr_i, col, bl0_ui, g0_i, b0_i, hi, NITEM);
    aggfin_kernel<4, true><<<ag, 256>>>(Mi, Qu, ptr_u, col, bl0_iu, g0_u, b0_u, hu, NUSER);

    // ---- layer 1: concatenated source-side GEMMs (N=128, split 64/64) ----
    gemm_kernel<128, 64, false><<<gm, 256, smem128>>>(hu, Wl1_ui, Wr1_iu, nullptr, Mu, Qu, NUSER, 128);
    gemm_kernel<128, 64, false><<<gm, 256, smem128>>>(hi, Wl1_iu, Wr1_ui, nullptr, Mi, Qi, NITEM, 128);

    aggfin_kernel<2, false><<<ag, 256>>>(Mu, Qi, ptr_i, col, bl1_ui, g1_i, b1_i, out_i, NITEM);
    aggfin_kernel<2, false><<<ag, 256>>>(Mi, Qu, ptr_u, col, bl1_iu, g1_u, b1_u, out_u, NUSER);
}